// round 5
// baseline (speedup 1.0000x reference)
#include <cuda_runtime.h>
#include <cuda_bf16.h>
#include <math.h>

#define T_DIM 1024
#define S_DIM 128
#define H_DIM 512
#define LN_EPS 1e-5f

// Scratch (allocation-free rule: __device__ globals)
__device__ float d_gt[T_DIM * H_DIM];   // text   @ wt^T  (1024 x 512)
__device__ float d_gs[S_DIM * H_DIM];   // struct @ ws^T  (128  x 512)

// ---------------------------------------------------------------------------
// Combined GEMM for gt and gs in ONE launch (unchanged — fuse dominates).
// ---------------------------------------------------------------------------
#define GM 64
#define GN 32
#define GK 32

__global__ __launch_bounds__(128) void gemm_all_kernel(
    const float* __restrict__ text, const float* __restrict__ sstruct,
    const float* __restrict__ W)
{
    __shared__ float As[GM][GK + 1];
    __shared__ float Bs[GN][GK + 1];

    const int tid = threadIdx.x;
    const int tx  = tid & 7;
    const int ty  = tid >> 3;
    const int bcol  = blockIdx.x * GN;
    const int browg = blockIdx.y * GM;

    const float* __restrict__ A;
    float* __restrict__ C;
    int arow, woff;
    if (browg < T_DIM) { A = text;    arow = browg;          woff = 0;     C = d_gt; }
    else               { A = sstruct; arow = browg - T_DIM;  woff = H_DIM; C = d_gs; }

    float acc[4][4];
    #pragma unroll
    for (int i = 0; i < 4; i++)
        #pragma unroll
        for (int j = 0; j < 4; j++) acc[i][j] = 0.f;

    for (int k0 = 0; k0 < H_DIM; k0 += GK) {
        #pragma unroll
        for (int i = 0; i < 4; i++) {
            int lin = tid + i * 128;
            int r   = lin >> 3;
            int c4  = (lin & 7) * 4;
            float4 v = *(const float4*)(A + (size_t)(arow + r) * H_DIM + k0 + c4);
            As[r][c4]     = v.x; As[r][c4 + 1] = v.y;
            As[r][c4 + 2] = v.z; As[r][c4 + 3] = v.w;
        }
        #pragma unroll
        for (int i = 0; i < 2; i++) {
            int lin = tid + i * 128;
            int r   = lin >> 3;
            int c4  = (lin & 7) * 4;
            float4 v = *(const float4*)(W + (size_t)(bcol + r) * 1024 + woff + k0 + c4);
            Bs[r][c4]     = v.x; Bs[r][c4 + 1] = v.y;
            Bs[r][c4 + 2] = v.z; Bs[r][c4 + 3] = v.w;
        }
        __syncthreads();

        #pragma unroll
        for (int k = 0; k < GK; k++) {
            float a[4], b[4];
            #pragma unroll
            for (int i = 0; i < 4; i++) a[i] = As[ty * 4 + i][k];
            #pragma unroll
            for (int j = 0; j < 4; j++) b[j] = Bs[tx * 4 + j][k];
            #pragma unroll
            for (int i = 0; i < 4; i++)
                #pragma unroll
                for (int j = 0; j < 4; j++)
                    acc[i][j] = fmaf(a[i], b[j], acc[i][j]);
        }
        __syncthreads();
    }

    #pragma unroll
    for (int i = 0; i < 4; i++) {
        float4 v = make_float4(acc[i][0], acc[i][1], acc[i][2], acc[i][3]);
        *(float4*)(C + (size_t)(arow + ty * 4 + i) * H_DIM + bcol + tx * 4) = v;
    }
}

// ---------------------------------------------------------------------------
// fuse2: store-only hot loop.
// Grid: x = H/HC h-chunks (16), y = T/TT t-tiles (16) -> 256 blocks.
// Block stages gs/struct chunks (S x HC) in smem; s-loop reads ONLY smem +
// L1-broadcast mask, writes gates (STG.128 streaming) and accumulates
// enrichment in registers. x = text + enrichment written to `enriched`
// (pre-LN); LayerNorm runs as a separate tiny pass.
// ---------------------------------------------------------------------------
#define HC 32   // floats per h-chunk (8 float4)
#define TT 64   // t-rows per block

__global__ __launch_bounds__(256) void fuse2_kernel(
    const float* __restrict__ text,
    const float* __restrict__ sstruct,
    const int*   __restrict__ mask,
    const float* __restrict__ gate_b,
    float* __restrict__ xout,       // (T, H) = text + enrichment (pre-LN)
    float* __restrict__ gates)      // (T, S, H)
{
    __shared__ float gs_s[S_DIM][HC];   // 16 KB
    __shared__ float st_s[S_DIM][HC];   // 16 KB

    const int tid = threadIdx.x;
    const int hx  = tid & 7;            // float4 index within chunk
    const int ts  = tid >> 3;           // 0..31 t-slot
    const int h0  = blockIdx.x * HC;
    const int t0  = blockIdx.y * TT;

    // Stage chunks: S*HC/4 = 1024 float4, 4 per thread
    #pragma unroll
    for (int i = tid; i < S_DIM * (HC / 4); i += 256) {
        int s  = i >> 3;
        int c4 = (i & 7) * 4;
        *(float4*)&gs_s[s][c4] = *(const float4*)(d_gs    + (size_t)s * H_DIM + h0 + c4);
        *(float4*)&st_s[s][c4] = *(const float4*)(sstruct + (size_t)s * H_DIM + h0 + c4);
    }
    __syncthreads();

    const int h  = h0 + hx * 4;
    const int r0 = t0 + ts;
    const int r1 = t0 + ts + 32;

    const float4 bias = *(const float4*)(gate_b + h);

    float4 gtb0, gtb1;
    {
        float4 a = *(const float4*)(d_gt + (size_t)r0 * H_DIM + h);
        float4 b = *(const float4*)(d_gt + (size_t)r1 * H_DIM + h);
        gtb0 = make_float4(a.x + bias.x, a.y + bias.y, a.z + bias.z, a.w + bias.w);
        gtb1 = make_float4(b.x + bias.x, b.y + bias.y, b.z + bias.z, b.w + bias.w);
    }
    float4 acc0 = make_float4(0.f, 0.f, 0.f, 0.f);
    float4 acc1 = make_float4(0.f, 0.f, 0.f, 0.f);

    const int* __restrict__ m0p = mask + (size_t)r0 * S_DIM;
    const int* __restrict__ m1p = mask + (size_t)r1 * S_DIM;
    float* __restrict__ g0p = gates + (size_t)r0 * S_DIM * H_DIM + h;
    float* __restrict__ g1p = gates + (size_t)r1 * S_DIM * H_DIM + h;

    #pragma unroll 4
    for (int s = 0; s < S_DIM; s++) {
        const float4 gs4 = *(const float4*)&gs_s[s][hx * 4];
        const float4 sv4 = *(const float4*)&st_s[s][hx * 4];
        const bool m0 = (m0p[s] != 0);
        const bool m1 = (m1p[s] != 0);

        float4 g0, g1;
        g0.x = m0 ? fmaxf(gtb0.x + gs4.x, 0.f) : 0.f;
        g0.y = m0 ? fmaxf(gtb0.y + gs4.y, 0.f) : 0.f;
        g0.z = m0 ? fmaxf(gtb0.z + gs4.z, 0.f) : 0.f;
        g0.w = m0 ? fmaxf(gtb0.w + gs4.w, 0.f) : 0.f;
        g1.x = m1 ? fmaxf(gtb1.x + gs4.x, 0.f) : 0.f;
        g1.y = m1 ? fmaxf(gtb1.y + gs4.y, 0.f) : 0.f;
        g1.z = m1 ? fmaxf(gtb1.z + gs4.z, 0.f) : 0.f;
        g1.w = m1 ? fmaxf(gtb1.w + gs4.w, 0.f) : 0.f;

        __stcs((float4*)(g0p + (size_t)s * H_DIM), g0);
        __stcs((float4*)(g1p + (size_t)s * H_DIM), g1);

        acc0.x = fmaf(g0.x, sv4.x, acc0.x);
        acc0.y = fmaf(g0.y, sv4.y, acc0.y);
        acc0.z = fmaf(g0.z, sv4.z, acc0.z);
        acc0.w = fmaf(g0.w, sv4.w, acc0.w);
        acc1.x = fmaf(g1.x, sv4.x, acc1.x);
        acc1.y = fmaf(g1.y, sv4.y, acc1.y);
        acc1.z = fmaf(g1.z, sv4.z, acc1.z);
        acc1.w = fmaf(g1.w, sv4.w, acc1.w);
    }

    // x = text + enrichment  (pre-LN), this thread exclusively owns (r,h..h+3)
    {
        float4 t4 = *(const float4*)(text + (size_t)r0 * H_DIM + h);
        float4 x;
        x.x = t4.x + acc0.x; x.y = t4.y + acc0.y;
        x.z = t4.z + acc0.z; x.w = t4.w + acc0.w;
        *(float4*)(xout + (size_t)r0 * H_DIM + h) = x;
    }
    {
        float4 t4 = *(const float4*)(text + (size_t)r1 * H_DIM + h);
        float4 x;
        x.x = t4.x + acc1.x; x.y = t4.y + acc1.y;
        x.z = t4.z + acc1.z; x.w = t4.w + acc1.w;
        *(float4*)(xout + (size_t)r1 * H_DIM + h) = x;
    }
}

// ---------------------------------------------------------------------------
// In-place LayerNorm over rows of x (written by fuse2 into `enriched`).
// 256 threads, 2 rows per block (128 threads = 4 warps per row).
// ---------------------------------------------------------------------------
__global__ __launch_bounds__(256) void ln_kernel(
    float* __restrict__ x,          // (T, H) in/out
    const float* __restrict__ gamma,
    const float* __restrict__ beta)
{
    const int tid = threadIdx.x;
    const int h4  = tid & 127;
    const int tg  = tid >> 7;
    const int h   = h4 * 4;
    const int r   = blockIdx.x * 2 + tg;

    __shared__ float red[2][2][4];

    float4 v = *(const float4*)(x + (size_t)r * H_DIM + h);
    float s1 = v.x + v.y + v.z + v.w;
    float s2 = v.x * v.x + v.y * v.y + v.z * v.z + v.w * v.w;

    const int lane = tid & 31;
    const int wg   = (tid >> 5) & 3;
    #pragma unroll
    for (int o = 16; o > 0; o >>= 1) {
        s1 += __shfl_xor_sync(0xFFFFFFFFu, s1, o);
        s2 += __shfl_xor_sync(0xFFFFFFFFu, s2, o);
    }
    if (lane == 0) { red[0][tg][wg] = s1; red[1][tg][wg] = s2; }
    __syncthreads();

    s1 = red[0][tg][0] + red[0][tg][1] + red[0][tg][2] + red[0][tg][3];
    s2 = red[1][tg][0] + red[1][tg][1] + red[1][tg][2] + red[1][tg][3];
    float mu  = s1 * (1.f / H_DIM);
    float var = s2 * (1.f / H_DIM) - mu * mu;
    float inv = rsqrtf(var + LN_EPS);

    const float4 gm = *(const float4*)(gamma + h);
    const float4 bt = *(const float4*)(beta  + h);
    float4 o;
    o.x = (v.x - mu) * inv * gm.x + bt.x;
    o.y = (v.y - mu) * inv * gm.y + bt.y;
    o.z = (v.z - mu) * inv * gm.z + bt.z;
    o.w = (v.w - mu) * inv * gm.w + bt.w;
    *(float4*)(x + (size_t)r * H_DIM + h) = o;
}

// ---------------------------------------------------------------------------
extern "C" void kernel_launch(void* const* d_in, const int* in_sizes, int n_in,
                              void* d_out, int out_size)
{
    const float* text    = (const float*)d_in[0];
    const float* sstruct = (const float*)d_in[1];
    const int*   mask    = (const int*)  d_in[2];
    const float* gate_w  = (const float*)d_in[3];
    const float* gate_b  = (const float*)d_in[4];
    const float* gamma   = (const float*)d_in[5];
    const float* beta    = (const float*)d_in[6];

    float* enriched = (float*)d_out;
    float* gates    = (float*)d_out + (size_t)T_DIM * H_DIM;

    {
        dim3 grd(H_DIM / GN, (T_DIM + S_DIM) / GM);   // 16 x 18 = 288 blocks
        gemm_all_kernel<<<grd, 128>>>(text, sstruct, gate_w);
    }
    {
        dim3 grd(H_DIM / HC, T_DIM / TT);             // 16 x 16 = 256 blocks
        fuse2_kernel<<<grd, 256>>>(text, sstruct, mask, gate_b,
                                   enriched, gates);
    }
    {
        ln_kernel<<<T_DIM / 2, 256>>>(enriched, gamma, beta);
    }
}